// round 4
// baseline (speedup 1.0000x reference)
#include <cuda_runtime.h>

#define NB 32
#define S 64
#define S2 (S*S)
#define S3 (S*S*S)
#define NPTS 65536
#define GRID_ELEMS (NB*S3)

// 21-tap Gaussian, sigma=3, normalized (computed in double precision)
__device__ __constant__ float W[21] = {
    5.143166e-04f, 1.477931e-03f, 3.800325e-03f, 8.744478e-03f,
    1.800486e-02f, 3.317359e-02f, 5.469392e-02f, 8.069228e-02f,
    1.065293e-01f, 1.258494e-01f, 1.330392e-01f, 1.258494e-01f,
    1.065293e-01f, 8.069228e-02f, 5.469392e-02f, 3.317359e-02f,
    1.800486e-02f, 8.744478e-03f, 3.800325e-03f, 1.477931e-03f,
    5.143166e-04f };

__device__ float g_vox[GRID_ELEMS];   // scatter target (left zeroed by convxy)
__device__ float g_tmp[GRID_ELEMS];   // convXY output

// Value-stationary 21-tap conv: 16 accumulators, each input read once.
#define CONV16(LOADEXPR, OUTSTMT)                                        \
    {                                                                    \
        float o[16];                                                     \
        _Pragma("unroll") for (int j = 0; j < 16; j++) o[j] = 0.0f;      \
        _Pragma("unroll") for (int m = 0; m < 36; m++) {                 \
            float v = (LOADEXPR);                                        \
            const int jlo = (m > 20) ? (m - 20) : 0;                     \
            const int jhi = (m < 15) ? m : 15;                           \
            _Pragma("unroll") for (int j = jlo; j <= jhi; j++)           \
                o[j] = fmaf(v, W[m - j], o[j]);                          \
        }                                                                \
        _Pragma("unroll") for (int j = 0; j < 16; j++) { OUTSTMT; }      \
    }

// ---------------------------------------------------------------------------
// Rotate points + trilinear scatter. Fast path: all 8 cells in-bounds ->
// one red.global.add.v4.f32 per (dz,dy) row (the two x-cells live in one
// aligned quad when (ix&3)<3; else quad red + 1 scalar red).
// ---------------------------------------------------------------------------
__global__ void k_scatter(const float* __restrict__ pc,
                          const float* __restrict__ rot) {
    int t = threadIdx.x;
    int b = blockIdx.x >> 8;                     // 256 blocks per batch
    __shared__ float R[9];
    __shared__ float sp[768];                    // 256 points * 3
    if (t < 9) R[t] = rot[b * 9 + t];
    const float* pblk = pc + (size_t)blockIdx.x * 768;
    sp[t]       = pblk[t];
    sp[t + 256] = pblk[t + 256];
    sp[t + 512] = pblk[t + 512];
    __syncthreads();

    float px = sp[t * 3 + 0];
    float py = sp[t * 3 + 1];
    float pz = sp[t * 3 + 2];

    float tx = fmaf(px, R[0], fmaf(py, R[1], pz * R[2]));
    float ty = fmaf(px, R[3], fmaf(py, R[4], pz * R[5]));
    float tz = fmaf(px, R[6], fmaf(py, R[7], pz * R[8]));

    float gx = (tx + 0.5f) * 63.0f;
    float gy = (ty + 0.5f) * 63.0f;
    float gz = (tz + 0.5f) * 63.0f;
    float fx = floorf(gx), fy = floorf(gy), fz = floorf(gz);
    int ix = (int)fx, iy = (int)fy, iz = (int)fz;
    float ax = gx - fx, ay = gy - fy, az = gz - fz;

    float wx0 = 1.0f - ax, wx1 = ax;
    float wy[2] = {1.0f - ay, ay};
    float wz[2] = {1.0f - az, az};

    float* base = g_vox + (size_t)b * S3;

    bool fast = (ix >= 0) & (ix <= 62) & (iy >= 0) & (iy <= 62) &
                (iz >= 0) & (iz <= 62);
    if (fast) {
        int l  = ix & 3;
        int qb = ix & ~3;
        float q0 = (l == 0) ? wx0 : 0.0f;
        float q1 = (l == 0) ? wx1 : ((l == 1) ? wx0 : 0.0f);
        float q2 = (l == 1) ? wx1 : ((l == 2) ? wx0 : 0.0f);
        float q3 = (l == 2) ? wx1 : ((l == 3) ? wx0 : 0.0f);
        // when l==3, the second x-cell spills into the next quad (qb+4 <= 60)
#pragma unroll
        for (int c = 0; c < 4; c++) {
            int dy = c & 1, dz = c >> 1;
            float wr = wy[dy] * wz[dz];
            float* p = base + (iz + dz) * S2 + (iy + dy) * S + qb;
            asm volatile("red.global.add.v4.f32 [%0], {%1,%2,%3,%4};"
                         :: "l"(p), "f"(wr * q0), "f"(wr * q1),
                            "f"(wr * q2), "f"(wr * q3) : "memory");
            if (l == 3)
                asm volatile("red.global.add.f32 [%0], %1;"
                             :: "l"(p + 4), "f"(wr * wx1) : "memory");
        }
    } else {
        float wxp[2] = {wx0, wx1};
#pragma unroll
        for (int c = 0; c < 8; c++) {
            int dx = c & 1, dy = (c >> 1) & 1, dz = c >> 2;
            int X = ix + dx, Y = iy + dy, Z = iz + dz;
            if ((unsigned)X < S && (unsigned)Y < S && (unsigned)Z < S) {
                atomicAdd(base + Z * S2 + Y * S + X,
                          wxp[dx] * wy[dy] * wz[dz]);
            }
        }
    }
}

// ---------------------------------------------------------------------------
// Fused conv along X then Y (clip raw voxels on load, re-zero grid for the
// next graph replay). One block per (b,z).
// ---------------------------------------------------------------------------
__global__ void __launch_bounds__(256) k_convxy() {
    int bz = blockIdx.x;
    float* src = g_vox + (size_t)bz * S2;
    float* dst = g_tmp + (size_t)bz * S2;
    __shared__ float A[S * 85];      // [y][x+10], x pads zeroed
    __shared__ float B[84 * 65];     // [y+10][x], y pads zeroed
    int t = threadIdx.x;

    for (int i = t; i < S * 85; i += 256) A[i] = 0.0f;
    for (int i = t; i < 10 * 65; i += 256) { B[i] = 0.0f; B[74 * 65 + i] = 0.0f; }
    __syncthreads();
    for (int i = t; i < S2; i += 256) {
        int y = i >> 6, x = i & 63;
        float v = src[i];
        src[i] = 0.0f;               // leave grid zeroed for next invocation
        A[y * 85 + x + 10] = fminf(fmaxf(v, 0.0f), 1.0f);
    }
    __syncthreads();

    {   // conv X: warp = 32 consecutive y (stride 85 -> conflict-free)
        int y  = t & 63;
        int x0 = (t >> 6) * 16;
        const float* row = A + y * 85 + x0;
        float* brow = B + (y + 10) * 65 + x0;
        CONV16(row[m], brow[j] = o[j]);
    }
    __syncthreads();

    {   // conv Y: warp = 32 consecutive x (stride 1 -> conflict-free)
        int x  = t & 63;
        int y0 = (t >> 6) * 16;
        const float* col = B + y0 * 65 + x;
        float* d = dst + y0 * S + x;
        CONV16(col[m * 65], d[j * S] = o[j]);
    }
}

// ---------------------------------------------------------------------------
// Conv along Z + scale + clip + DRC product + flip. One block per (b,y).
// out[b, 63-y, x] = 1 - prod_z (1 - clip(scale_b * convz[z,x]))
// ---------------------------------------------------------------------------
__global__ void __launch_bounds__(256) k_convz(const float* __restrict__ scale,
                                               float* __restrict__ out) {
    int by = blockIdx.x;
    int b = by >> 6, y = by & 63;
    const float* src = g_tmp + (size_t)b * S3 + y * S;   // + z*S2 + x
    __shared__ float Bz[84 * 65];    // [z+10][x]
    __shared__ float part[4][S];
    int t = threadIdx.x;

    for (int i = t; i < 10 * 65; i += 256) { Bz[i] = 0.0f; Bz[74 * 65 + i] = 0.0f; }
    for (int i = t; i < S2; i += 256) {
        int z = i >> 6, x = i & 63;
        Bz[(z + 10) * 65 + x] = src[(size_t)z * S2 + x];
    }
    __syncthreads();

    float sc = scale[b];
    int x  = t & 63;
    int z0 = (t >> 6) * 16;
    const float* col = Bz + z0 * 65 + x;

    float T = 1.0f;
    CONV16(col[m * 65],
           { float a = fminf(fmaxf(o[j] * sc, 0.0f), 1.0f); T *= (1.0f - a); });

    part[t >> 6][x] = T;
    __syncthreads();
    if (t < 64) {
        float Tt = part[0][x] * part[1][x] * part[2][x] * part[3][x];
        out[(size_t)b * S2 + (63 - y) * S + x] = 1.0f - Tt;
    }
}

// ---------------------------------------------------------------------------
extern "C" void kernel_launch(void* const* d_in, const int* in_sizes, int n_in,
                              void* d_out, int out_size) {
    const float* pc    = (const float*)d_in[0];
    const float* rot   = (const float*)d_in[1];
    const float* scale = (const float*)d_in[2];
    float* out = (float*)d_out;

    k_scatter<<<NB * NPTS / 256, 256>>>(pc, rot);
    k_convxy<<<NB * S, 256>>>();
    k_convz<<<NB * S, 256>>>(scale, out);
}

// round 5
// speedup vs baseline: 2.1074x; 2.1074x over previous
#include <cuda_runtime.h>

#define NB 32
#define S 64
#define S2 (S*S)
#define S3 (S*S*S)
#define NPTS 65536
#define GRID_ELEMS (NB*S3)

// 21-tap Gaussian, sigma=3, normalized (computed in double precision)
__device__ __constant__ float W[21] = {
    5.143166e-04f, 1.477931e-03f, 3.800325e-03f, 8.744478e-03f,
    1.800486e-02f, 3.317359e-02f, 5.469392e-02f, 8.069228e-02f,
    1.065293e-01f, 1.258494e-01f, 1.330392e-01f, 1.258494e-01f,
    1.065293e-01f, 8.069228e-02f, 5.469392e-02f, 3.317359e-02f,
    1.800486e-02f, 8.744478e-03f, 3.800325e-03f, 1.477931e-03f,
    5.143166e-04f };

__device__ float g_vox[GRID_ELEMS];   // scatter target; re-zeroed by k_convz
__device__ float g_tmp[GRID_ELEMS];   // convXY output, layout [b][y][z][x]

// Value-stationary 21-tap conv: 16 accumulators, each input read once.
#define CONV16(LOADEXPR, OUTSTMT)                                        \
    {                                                                    \
        float o[16];                                                     \
        _Pragma("unroll") for (int j = 0; j < 16; j++) o[j] = 0.0f;      \
        _Pragma("unroll") for (int m = 0; m < 36; m++) {                 \
            float v = (LOADEXPR);                                        \
            const int jlo = (m > 20) ? (m - 20) : 0;                     \
            const int jhi = (m < 15) ? m : 15;                           \
            _Pragma("unroll") for (int j = jlo; j <= jhi; j++)           \
                o[j] = fmaf(v, W[m - j], o[j]);                          \
        }                                                                \
        _Pragma("unroll") for (int j = 0; j < 16; j++) { OUTSTMT; }      \
    }

// ---------------------------------------------------------------------------
// Rotate points + trilinear scatter (8 scalar atomics; LTS-lane-bound floor).
// ---------------------------------------------------------------------------
__global__ void k_scatter(const float* __restrict__ pc,
                          const float* __restrict__ rot) {
    int t = threadIdx.x;
    int b = blockIdx.x >> 8;                     // 256 blocks per batch
    __shared__ float R[9];
    __shared__ float sp[768];                    // 256 points * 3
    if (t < 9) R[t] = rot[b * 9 + t];
    const float* pblk = pc + (size_t)blockIdx.x * 768;
    sp[t]       = pblk[t];
    sp[t + 256] = pblk[t + 256];
    sp[t + 512] = pblk[t + 512];
    __syncthreads();

    float px = sp[t * 3 + 0];
    float py = sp[t * 3 + 1];
    float pz = sp[t * 3 + 2];

    float tx = fmaf(px, R[0], fmaf(py, R[1], pz * R[2]));
    float ty = fmaf(px, R[3], fmaf(py, R[4], pz * R[5]));
    float tz = fmaf(px, R[6], fmaf(py, R[7], pz * R[8]));

    float gx = (tx + 0.5f) * 63.0f;
    float gy = (ty + 0.5f) * 63.0f;
    float gz = (tz + 0.5f) * 63.0f;
    float fx = floorf(gx), fy = floorf(gy), fz = floorf(gz);
    int ix = (int)fx, iy = (int)fy, iz = (int)fz;
    float ax = gx - fx, ay = gy - fy, az = gz - fz;

    float wx[2] = {1.0f - ax, ax};
    float wy[2] = {1.0f - ay, ay};
    float wz[2] = {1.0f - az, az};

    float* base = g_vox + (size_t)b * S3;
#pragma unroll
    for (int c = 0; c < 8; c++) {
        int dx = c & 1, dy = (c >> 1) & 1, dz = c >> 2;
        int X = ix + dx, Y = iy + dy, Z = iz + dz;
        if ((unsigned)X < S && (unsigned)Y < S && (unsigned)Z < S) {
            atomicAdd(base + Z * S2 + Y * S + X, wx[dx] * wy[dy] * wz[dz]);
        }
    }
}

// ---------------------------------------------------------------------------
// Fused conv along X then Y (clip raw voxels on load). One block per (b,z).
// Output layout transposed: g_tmp[b][y][z][x] so convz reads contiguously.
// ---------------------------------------------------------------------------
__global__ void __launch_bounds__(256) k_convxy() {
    int bz = blockIdx.x;
    int b = bz >> 6, z = bz & 63;
    const float* src = g_vox + (size_t)bz * S2;
    float* dstb = g_tmp + ((size_t)b * S + 0) * S2 + z * S;  // + y*S2 + x
    __shared__ float A[S * 85];      // [y][x+10], x pads zeroed
    __shared__ float B[84 * 65];     // [y+10][x], y pads zeroed
    int t = threadIdx.x;

    for (int i = t; i < S * 85; i += 256) A[i] = 0.0f;
    for (int i = t; i < 10 * 65; i += 256) { B[i] = 0.0f; B[74 * 65 + i] = 0.0f; }
    __syncthreads();
    for (int i = t; i < S2; i += 256) {
        int y = i >> 6, x = i & 63;
        float v = src[i];
        A[y * 85 + x + 10] = fminf(fmaxf(v, 0.0f), 1.0f);
    }
    __syncthreads();

    {   // conv X: warp = 32 consecutive y (stride 85 -> conflict-free)
        int y  = t & 63;
        int x0 = (t >> 6) * 16;
        const float* row = A + y * 85 + x0;
        float* brow = B + (y + 10) * 65 + x0;
        CONV16(row[m], brow[j] = o[j]);
    }
    __syncthreads();

    {   // conv Y: warp = 32 consecutive x (stride 1 -> conflict-free)
        int x  = t & 63;
        int y0 = (t >> 6) * 16;
        const float* col = B + y0 * 65 + x;
        float* d = dstb + (size_t)y0 * S2 + x;     // [b][y][z][x]
        CONV16(col[m * 65], d[(size_t)j * S2] = o[j]);
    }
}

// ---------------------------------------------------------------------------
// Conv along Z + scale + clip + DRC product + flip. One block per (b,y).
// Reads g_tmp[b][y][:][:] contiguously (16KB). Also re-zeroes its 16KB chunk
// of g_vox for the next graph replay.
// ---------------------------------------------------------------------------
__global__ void __launch_bounds__(256) k_convz(const float* __restrict__ scale,
                                               float* __restrict__ out) {
    int by = blockIdx.x;
    int b = by >> 6, y = by & 63;
    const float* src = g_tmp + (size_t)by * S2;     // [z][x] contiguous
    __shared__ float Bz[84 * 65];    // [z+10][x]
    __shared__ float part[4][S];
    int t = threadIdx.x;

    for (int i = t; i < 10 * 65; i += 256) { Bz[i] = 0.0f; Bz[74 * 65 + i] = 0.0f; }
    for (int i = t; i < S2; i += 256) {
        int z = i >> 6, x = i & 63;
        Bz[(z + 10) * 65 + x] = src[i];
    }
    // Re-zero this block's chunk of the voxel grid (fire-and-forget stores).
    {
        float4* vz = reinterpret_cast<float4*>(g_vox + (size_t)by * S2);
#pragma unroll
        for (int i = 0; i < 4; i++)
            vz[t + 256 * i] = make_float4(0.f, 0.f, 0.f, 0.f);
    }
    __syncthreads();

    float sc = scale[b];
    int x  = t & 63;
    int z0 = (t >> 6) * 16;
    const float* col = Bz + z0 * 65 + x;

    float T = 1.0f;
    CONV16(col[m * 65],
           { float a = fminf(fmaxf(o[j] * sc, 0.0f), 1.0f); T *= (1.0f - a); });

    part[t >> 6][x] = T;
    __syncthreads();
    if (t < 64) {
        float Tt = part[0][x] * part[1][x] * part[2][x] * part[3][x];
        out[(size_t)b * S2 + (63 - y) * S + x] = 1.0f - Tt;
    }
}

// ---------------------------------------------------------------------------
extern "C" void kernel_launch(void* const* d_in, const int* in_sizes, int n_in,
                              void* d_out, int out_size) {
    const float* pc    = (const float*)d_in[0];
    const float* rot   = (const float*)d_in[1];
    const float* scale = (const float*)d_in[2];
    float* out = (float*)d_out;

    k_scatter<<<NB * NPTS / 256, 256>>>(pc, rot);
    k_convxy<<<NB * S, 256>>>();
    k_convz<<<NB * S, 256>>>(scale, out);
}